// round 10
// baseline (speedup 1.0000x reference)
#include <cuda_runtime.h>

#define SQ 2048
#define BB 2
#define NH 12
#define DK 5
#define DM 64
#define DI 60
#define BHN (BB*NH)   // 24

typedef unsigned long long ull;

__device__ __forceinline__ ull fma2(ull a, ull b, ull c){ ull d; asm("fma.rn.f32x2 %0,%1,%2,%3;":"=l"(d):"l"(a),"l"(b),"l"(c)); return d; }
__device__ __forceinline__ ull add2(ull a, ull b){ ull d; asm("add.rn.f32x2 %0,%1,%2;":"=l"(d):"l"(a),"l"(b)); return d; }
__device__ __forceinline__ ull mul2(ull a, ull b){ ull d; asm("mul.rn.f32x2 %0,%1,%2;":"=l"(d):"l"(a),"l"(b)); return d; }
__device__ __forceinline__ ull pack2(float lo, float hi){ ull d; asm("mov.b64 %0,{%1,%2};":"=l"(d):"f"(lo),"f"(hi)); return d; }
__device__ __forceinline__ void unpack2(ull v, float& lo, float& hi){ asm("mov.b64 {%0,%1},%2;":"=f"(lo),"=f"(hi):"l"(v)); }
__device__ __forceinline__ float ex2a(float x){ float y; asm("ex2.approx.f32 %0,%1;":"=f"(y):"f"(x)); return y; }
__device__ __forceinline__ float rcpa(float x){ float y; asm("rcp.approx.f32 %0,%1;":"=f"(y):"f"(x)); return y; }
__device__ __forceinline__ void ldcs2(const float* p, ull& a, ull& b){ asm("ld.global.cs.v2.b64 {%0,%1},[%2];":"=l"(a),"=l"(b):"l"(p)); }
__device__ __forceinline__ void stcs2(float* p, ull a, ull b){ asm("st.global.cs.v2.b64 [%0],{%1,%2};"::"l"(p),"l"(a),"l"(b):"memory"); }

// Scratch (device globals; no allocations allowed)
__device__ float g_q[BHN*SQ*DK];    // [B,H,S,DK], pre-scaled by log2e/sqrt(DK)
__device__ float g_k[BHN*DK*SQ];    // [B,H,DK,S]
__device__ float g_v[BHN*DK*SQ];    // [B,H,DK,S]
__device__ float g_ctx[BB*SQ*DI];   // [B,S,60]

// ---------------------------------------------------------------------------
// Kernel 1: QKV projections. 32 rows/block, 256 threads, grid (128, 3).
// Transposed padded weights Wt[60][68] -> conflict-free LDS.128; float4 X
// broadcast. Lane computes channels {lane, lane+32}.
// ---------------------------------------------------------------------------
__global__ __launch_bounds__(256) void proj_kernel(
    const float* __restrict__ Q, const float* __restrict__ K, const float* __restrict__ V,
    const float* __restrict__ Wq, const float* __restrict__ bq,
    const float* __restrict__ Wk, const float* __restrict__ bk,
    const float* __restrict__ Wv, const float* __restrict__ bv)
{
    __shared__ float Wt[DI][68];   // transposed, padded: 16.3 KB
    __shared__ float bs[DI];
    __shared__ float Xs[32][DM];   // 8 KB

    int mode = blockIdx.y;
    const float* X; const float* W; const float* bvec;
    if (mode == 0)      { X = Q; W = Wq; bvec = bq; }
    else if (mode == 1) { X = K; W = Wk; bvec = bk; }
    else                { X = V; W = Wv; bvec = bv; }

    int rowbase = blockIdx.x * 32;
    int tid = threadIdx.x;

    for (int idx = tid; idx < DM*DI; idx += 256) {
        int m = idx / DI, o = idx - m*DI;
        Wt[o][m] = W[idx];
    }
    for (int i = tid; i < 32*DM/4; i += 256)
        ((float4*)Xs)[i] = ((const float4*)(X + rowbase*DM))[i];
    if (tid < DI) bs[tid] = bvec[tid];
    __syncthreads();

    int w = tid >> 5, lane = tid & 31;
    int o2  = lane + 32;
    int o2c = (o2 < DI) ? o2 : 0;
    const float SCQ = 0.44721359549995793f * 1.4426950408889634f; // fold log2e

    #pragma unroll
    for (int rr = 0; rr < 4; rr++) {
        int r = w + rr*8;
        float acc1 = bs[lane];
        float acc2 = bs[o2c];
        #pragma unroll
        for (int mq = 0; mq < 16; mq++) {
            float4 x  = *(const float4*)&Xs[r][mq*4];
            float4 w1 = *(const float4*)&Wt[lane][mq*4];
            float4 w2 = *(const float4*)&Wt[o2c][mq*4];
            acc1 = fmaf(x.x, w1.x, acc1); acc1 = fmaf(x.y, w1.y, acc1);
            acc1 = fmaf(x.z, w1.z, acc1); acc1 = fmaf(x.w, w1.w, acc1);
            acc2 = fmaf(x.x, w2.x, acc2); acc2 = fmaf(x.y, w2.y, acc2);
            acc2 = fmaf(x.z, w2.z, acc2); acc2 = fmaf(x.w, w2.w, acc2);
        }
        int rg = rowbase + r;
        int b = rg >> 11, s = rg & (SQ-1);
        {
            int h = lane / DK, d = lane - h*DK;
            if (mode == 0)      g_q[((b*NH+h)*SQ + s)*DK + d] = acc1 * SCQ;
            else if (mode == 1) g_k[((b*NH+h)*DK + d)*SQ + s] = acc1;
            else                g_v[((b*NH+h)*DK + d)*SQ + s] = acc1;
        }
        if (o2 < DI) {
            int h = o2 / DK, d = o2 - h*DK;
            if (mode == 0)      g_q[((b*NH+h)*SQ + s)*DK + d] = acc2 * SCQ;
            else if (mode == 1) g_k[((b*NH+h)*DK + d)*SQ + s] = acc2;
            else                g_v[((b*NH+h)*DK + d)*SQ + s] = acc2;
        }
    }
}

// ---------------------------------------------------------------------------
// Kernel 2: fused scores + bias + softmax + attn write + ctx.
// grid (32, 24), 512 threads, 1 block/SM. Thread owns 4 consecutive cols
// (j = tid*4). K AND V in REGISTERS (f32x2-packed, loaded once from gmem,
// coalesced) -> zero LDS in the hot loop. q staged in smem. Distance-2 bias
// prefetch via parity ring. ctx partials via smem (triple-buffered), drained
// one pair later by 10 val-aligned warps. One barrier per pair.
// ---------------------------------------------------------------------------
__global__ __launch_bounds__(512) void attn_kernel(
    const float* __restrict__ bias,
    const float* __restrict__ lam_p,
    float* __restrict__ attn_out)
{
    __shared__ float qs[64*DK];          // 1.25 KB
    __shared__ float part[3][10][256];   // 30 KB
    __shared__ float2 redb[2][16];

    int bh = blockIdx.y, row0 = blockIdx.x*64;
    int tid = threadIdx.x, lane = tid & 31, wid = tid >> 5;
    float laml = lam_p[0] * 1.4426950408889634f;
    ull lam2 = pack2(laml, laml);

    const float* kg = g_k + (size_t)bh*DK*SQ;
    const float* vg = g_v + (size_t)bh*DK*SQ;
    const float* qg = g_q + ((size_t)bh*SQ + row0)*DK;
    int b = bh / NH, hh = bh % NH;

    for (int i = tid; i < 64*DK; i += 512) qs[i] = qg[i];

    int j = tid*4;
    ull k2[DK][2], v2[DK][2];
    #pragma unroll
    for (int d = 0; d < DK; d++) {
        ulonglong2 t = *(const ulonglong2*)(kg + d*SQ + j);
        k2[d][0] = t.x; k2[d][1] = t.y;
        ulonglong2 u = *(const ulonglong2*)(vg + d*SQ + j);
        v2[d][0] = u.x; v2[d][1] = u.y;
    }

    const float* bbase = bias     + ((size_t)bh*SQ + row0)*(size_t)SQ;
    float*       abase = attn_out + ((size_t)bh*SQ + row0)*(size_t)SQ;

    // distance-2 prefetch ring: bc[p&1] holds pair p's bias
    ull bc[2][2][2];   // [parity][row][colpair]
    ldcs2(bbase + j,        bc[0][0][0], bc[0][0][1]);
    ldcs2(bbase + SQ + j,   bc[0][1][0], bc[0][1][1]);
    ldcs2(bbase + 2*SQ + j, bc[1][0][0], bc[1][0][1]);
    ldcs2(bbase + 3*SQ + j, bc[1][1][0], bc[1][1][1]);

    float inv_prev0 = 0.f, inv_prev1 = 0.f;
    __syncthreads();   // qs ready

    for (int pair = 0; pair < 32; pair++) {
        int par = pair & 1;
        int p3 = pair % 3;

        ull q2[2][DK];
        #pragma unroll
        for (int r = 0; r < 2; r++)
            #pragma unroll
            for (int d = 0; d < DK; d++) {
                float qv = qs[(pair*2 + r)*DK + d];
                q2[r][d] = pack2(qv, qv);
            }

        ull e2[2][2], ce2[2][DK], ls2[2] = {0ull, 0ull};
        #pragma unroll
        for (int r = 0; r < 2; r++) {
            #pragma unroll
            for (int c = 0; c < 2; c++) {
                ull s2 = mul2(lam2, bc[par][r][c]);
                #pragma unroll
                for (int d = 0; d < DK; d++) s2 = fma2(q2[r][d], k2[d][c], s2);
                float slo, shi; unpack2(s2, slo, shi);
                ull e = pack2(ex2a(slo), ex2a(shi));
                e2[r][c] = e;
                ls2[r] = add2(ls2[r], e);
            }
        }
        #pragma unroll
        for (int r = 0; r < 2; r++) {
            #pragma unroll
            for (int d = 0; d < DK; d++) {
                ull acc = mul2(e2[r][0], v2[d][0]);
                ce2[r][d] = fma2(e2[r][1], v2[d][1], acc);
            }
        }

        // prefetch bias for pair+2 into slot par (consumed above)
        if (pair < 30) {
            const float* bn = bbase + (size_t)((pair+2)*2)*SQ;
            ldcs2(bn + j,      bc[par][0][0], bc[par][0][1]);
            ldcs2(bn + SQ + j, bc[par][1][0], bc[par][1][1]);
        }

        // row sums -> warp reduce -> redb (double-buffered)
        float ls0, ls1;
        { float a, bq_; unpack2(ls2[0], a, bq_); ls0 = a + bq_;
          unpack2(ls2[1], a, bq_); ls1 = a + bq_; }
        #pragma unroll
        for (int o = 16; o; o >>= 1) {
            ls0 += __shfl_xor_sync(0xffffffffu, ls0, o);
            ls1 += __shfl_xor_sync(0xffffffffu, ls1, o);
        }
        if (lane == 0) redb[par][wid] = make_float2(ls0, ls1);

        // ctx partials: horizontal + lane-pair reduce + STS (triple buffer)
        #pragma unroll
        for (int r = 0; r < 2; r++)
            #pragma unroll
            for (int d = 0; d < DK; d++) {
                float a, bq_; unpack2(ce2[r][d], a, bq_);
                float s = a + bq_;
                s += __shfl_xor_sync(0xffffffffu, s, 1);
                if (!(lane & 1)) part[p3][r*5 + d][tid >> 1] = s;
            }

        __syncthreads();   // the ONLY barrier per pair

        float t0 = 0.f, t1 = 0.f;
        #pragma unroll
        for (int w2 = 0; w2 < 16; w2++) { float2 v = redb[par][w2]; t0 += v.x; t1 += v.y; }
        float inv0 = rcpa(t0), inv1 = rcpa(t1);

        // drain previous pair's ctx partials (warp w handles value w)
        if (pair > 0 && tid < 320) {
            int pprev = (p3 == 0) ? 2 : p3 - 1;
            const float4* pp = (const float4*)&part[pprev][wid][lane*8];
            float4 x = pp[0], y = pp[1];
            float s = ((x.x+x.y)+(x.z+x.w)) + ((y.x+y.y)+(y.z+y.w));
            #pragma unroll
            for (int o = 16; o; o >>= 1) s += __shfl_xor_sync(0xffffffffu, s, o);
            if (lane == 0) {
                int r = (wid >= 5), d = wid - r*5;
                float ip = r ? inv_prev1 : inv_prev0;
                g_ctx[((size_t)b*SQ + row0 + (pair-1)*2 + r)*DI + hh*DK + d] = s * ip;
            }
        }

        // normalized attn store
        {
            ull i20 = pack2(inv0, inv0), i21 = pack2(inv1, inv1);
            float* a0 = abase + (size_t)(pair*2)*SQ;
            stcs2(a0 + j,      mul2(e2[0][0], i20), mul2(e2[0][1], i20));
            stcs2(a0 + SQ + j, mul2(e2[1][0], i21), mul2(e2[1][1], i21));
        }
        inv_prev0 = inv0; inv_prev1 = inv1;
    }

    // final drain: pair 31 partials (p3 = 31%3 = 1); visible via last barrier
    if (tid < 320) {
        const float4* pp = (const float4*)&part[31%3][wid][lane*8];
        float4 x = pp[0], y = pp[1];
        float s = ((x.x+x.y)+(x.z+x.w)) + ((y.x+y.y)+(y.z+y.w));
        #pragma unroll
        for (int o = 16; o; o >>= 1) s += __shfl_xor_sync(0xffffffffu, s, o);
        if (lane == 0) {
            int r = (wid >= 5), d = wid - r*5;
            float ip = r ? inv_prev1 : inv_prev0;
            g_ctx[((size_t)b*SQ + row0 + 62 + r)*DI + hh*DK + d] = s * ip;
        }
    }
}

// ---------------------------------------------------------------------------
// Kernel 3: out = residual + ctx @ Wo + bo. Warp-per-row, 16 rows/block.
// ---------------------------------------------------------------------------
__global__ __launch_bounds__(256) void out_kernel(
    const float* __restrict__ Qin, const float* __restrict__ Wo,
    const float* __restrict__ bo, float* __restrict__ out)
{
    __shared__ float Ws[DI*DM];
    __shared__ float bs[DM];
    __shared__ float Cs[16][DI];
    int tid = threadIdx.x;
    int rowbase = blockIdx.x * 16;
    for (int idx = tid; idx < DI*DM; idx += 256) Ws[idx] = Wo[idx];
    if (tid < DM) bs[tid] = bo[tid];
    for (int idx = tid; idx < 16*DI; idx += 256) Cs[idx/DI][idx%DI] = g_ctx[rowbase*DI + idx];
    __syncthreads();

    int w = tid >> 5, lane = tid & 31;
    #pragma unroll
    for (int rr = 0; rr < 2; rr++) {
        int r = w + rr*8;
        int rg = rowbase + r;
        float acc1 = bs[lane]      + Qin[rg*DM + lane];
        float acc2 = bs[lane + 32] + Qin[rg*DM + lane + 32];
        #pragma unroll 10
        for (int o = 0; o < DI; o++) {
            float c = Cs[r][o];
            acc1 = fmaf(c, Ws[o*DM + lane],      acc1);
            acc2 = fmaf(c, Ws[o*DM + lane + 32], acc2);
        }
        out[rg*DM + lane]      = acc1;
        out[rg*DM + lane + 32] = acc2;
    }
}

// ---------------------------------------------------------------------------
extern "C" void kernel_launch(void* const* d_in, const int* in_sizes, int n_in,
                              void* d_out, int out_size)
{
    const float* Q    = (const float*)d_in[0];
    const float* K    = (const float*)d_in[1];
    const float* V    = (const float*)d_in[2];
    const float* bias = (const float*)d_in[3];
    const float* lam  = (const float*)d_in[4];
    const float* Wq   = (const float*)d_in[5];
    const float* bq   = (const float*)d_in[6];
    const float* Wk   = (const float*)d_in[7];
    const float* bk   = (const float*)d_in[8];
    const float* Wv   = (const float*)d_in[9];
    const float* bv   = (const float*)d_in[10];
    const float* Wo   = (const float*)d_in[11];
    const float* bo   = (const float*)d_in[12];

    float* out1 = (float*)d_out;                 // [B,S,64]
    float* attn = out1 + (size_t)BB*SQ*DM;       // [B,H,S,S]

    proj_kernel<<<dim3(BB*SQ/32, 3), 256>>>(Q, K, V, Wq, bq, Wk, bk, Wv, bv);
    attn_kernel<<<dim3(SQ/64, BHN), 512>>>(bias, lam, attn);
    out_kernel<<<BB*SQ/16, 256>>>(Q, Wo, bo, out1);
}

// round 11
// speedup vs baseline: 1.6135x; 1.6135x over previous
#include <cuda_runtime.h>

#define SQ 2048
#define BB 2
#define NH 12
#define DK 5
#define DM 64
#define DI 60
#define BHN (BB*NH)   // 24

typedef unsigned long long ull;

__device__ __forceinline__ ull fma2(ull a, ull b, ull c){ ull d; asm("fma.rn.f32x2 %0,%1,%2,%3;":"=l"(d):"l"(a),"l"(b),"l"(c)); return d; }
__device__ __forceinline__ ull add2(ull a, ull b){ ull d; asm("add.rn.f32x2 %0,%1,%2;":"=l"(d):"l"(a),"l"(b)); return d; }
__device__ __forceinline__ ull mul2(ull a, ull b){ ull d; asm("mul.rn.f32x2 %0,%1,%2;":"=l"(d):"l"(a),"l"(b)); return d; }
__device__ __forceinline__ ull pack2(float lo, float hi){ ull d; asm("mov.b64 %0,{%1,%2};":"=l"(d):"f"(lo),"f"(hi)); return d; }
__device__ __forceinline__ void unpack2(ull v, float& lo, float& hi){ asm("mov.b64 {%0,%1},%2;":"=f"(lo),"=f"(hi):"l"(v)); }
__device__ __forceinline__ float ex2a(float x){ float y; asm("ex2.approx.f32 %0,%1;":"=f"(y):"f"(x)); return y; }
__device__ __forceinline__ float rcpa(float x){ float y; asm("rcp.approx.f32 %0,%1;":"=f"(y):"f"(x)); return y; }
__device__ __forceinline__ void ldcs2(const float* p, ull& a, ull& b){ asm("ld.global.cs.v2.b64 {%0,%1},[%2];":"=l"(a),"=l"(b):"l"(p)); }
__device__ __forceinline__ void stcs2(float* p, ull a, ull b){ asm("st.global.cs.v2.b64 [%0],{%1,%2};"::"l"(p),"l"(a),"l"(b):"memory"); }

// Scratch (device globals; no allocations allowed)
__device__ float g_q[BHN*SQ*DK];    // [B,H,S,DK], pre-scaled by log2e/sqrt(DK)
__device__ float g_k[BHN*DK*SQ];    // [B,H,DK,S]
__device__ float g_v[BHN*DK*SQ];    // [B,H,DK,S]
__device__ float g_ctx[BB*SQ*DI];   // [B,S,60]

// ---------------------------------------------------------------------------
// Kernel 1: QKV projections, warp-per-row. 64 rows/block, 512 threads,
// grid (64, 3). Lane computes channels {lane, lane+32}. (R8 version, known.)
// ---------------------------------------------------------------------------
__global__ __launch_bounds__(512) void proj_kernel(
    const float* __restrict__ Q, const float* __restrict__ K, const float* __restrict__ V,
    const float* __restrict__ Wq, const float* __restrict__ bq,
    const float* __restrict__ Wk, const float* __restrict__ bk,
    const float* __restrict__ Wv, const float* __restrict__ bv)
{
    __shared__ float Ws[DM*DI];   // 15.4 KB
    __shared__ float bs[DI];
    __shared__ float Xs[64][DM];  // 16 KB

    int mode = blockIdx.y;
    const float* X; const float* W; const float* bvec;
    if (mode == 0)      { X = Q; W = Wq; bvec = bq; }
    else if (mode == 1) { X = K; W = Wk; bvec = bk; }
    else                { X = V; W = Wv; bvec = bv; }

    int rowbase = blockIdx.x * 64;
    int tid = threadIdx.x;

    for (int idx = tid; idx < DM*DI; idx += 512) Ws[idx] = W[idx];
    for (int idx = tid; idx < 1024; idx += 512)
        ((float4*)Xs)[idx] = ((const float4*)(X + rowbase*DM))[idx];
    if (tid < DI) bs[tid] = bvec[tid];
    __syncthreads();

    int w = tid >> 5, lane = tid & 31;
    int o2  = lane + 32;
    int o2c = (o2 < DI) ? o2 : 0;
    const float SCQ = 0.44721359549995793f * 1.4426950408889634f; // fold log2e

    #pragma unroll
    for (int rr = 0; rr < 4; rr++) {
        int r = w + rr*16;
        float acc1 = bs[lane];
        float acc2 = bs[o2c];
        #pragma unroll 8
        for (int m = 0; m < DM; m++) {
            float x = Xs[r][m];
            acc1 = fmaf(x, Ws[m*DI + lane], acc1);
            acc2 = fmaf(x, Ws[m*DI + o2c],  acc2);
        }
        int rg = rowbase + r;
        int b = rg >> 11, s = rg & (SQ-1);
        {
            int h = lane / DK, d = lane - h*DK;
            if (mode == 0)      g_q[((b*NH+h)*SQ + s)*DK + d] = acc1 * SCQ;
            else if (mode == 1) g_k[((b*NH+h)*DK + d)*SQ + s] = acc1;
            else                g_v[((b*NH+h)*DK + d)*SQ + s] = acc1;
        }
        if (o2 < DI) {
            int h = o2 / DK, d = o2 - h*DK;
            if (mode == 0)      g_q[((b*NH+h)*SQ + s)*DK + d] = acc2 * SCQ;
            else if (mode == 1) g_k[((b*NH+h)*DK + d)*SQ + s] = acc2;
            else                g_v[((b*NH+h)*DK + d)*SQ + s] = acc2;
        }
    }
}

// ---------------------------------------------------------------------------
// Kernel 2: fused scores + bias + softmax + attn write + ctx.
// grid (32, 24), 256 threads, 2 blocks/SM. Thread owns 8 cols (2 float4s at
// j0=tid*4, j1=1024+tid*4). K in REGISTERS (loop-invariant, loaded once,
// coalesced); V in smem (40KB, 10 LDS.128/pair). Packed f32x2 math; q is
// broadcast-packed per row. ctx partials via smem (triple-buffered), drained
// one pair later by 160 threads, scaled by inv_prev. One barrier per pair.
// ---------------------------------------------------------------------------
#define ATTN_SMEM_FLOATS (5*SQ + 3*10*128 + 2*8*2)
#define ATTN_SMEM_BYTES  (ATTN_SMEM_FLOATS*4)

__global__ __launch_bounds__(256, 2) void attn_kernel(
    const float* __restrict__ bias,
    const float* __restrict__ lam_p,
    float* __restrict__ attn_out)
{
    extern __shared__ float sm[];
    float* Vsm  = sm;                 // [5][2048]  40KB
    float* part = sm + 5*SQ;          // [3][10][128]
    float* redb = part + 3*10*128;    // [2][8] float2

    int bh = blockIdx.y, row0 = blockIdx.x*64;
    int tid = threadIdx.x, lane = tid & 31, wid = tid >> 5;
    float laml = lam_p[0] * 1.4426950408889634f;
    ull lam2 = pack2(laml, laml);

    const float* kg = g_k + (size_t)bh*DK*SQ;
    const float* vg = g_v + (size_t)bh*DK*SQ;
    const float* qg = g_q + ((size_t)bh*SQ + row0)*DK;
    int b = bh / NH, hh = bh % NH;

    for (int i = tid; i < DK*SQ/4; i += 256)
        ((float4*)Vsm)[i] = ((const float4*)vg)[i];

    int j0 = tid*4, j1 = 1024 + tid*4;

    // K held in registers for all 32 pairs: [d][half*2+colpair]
    ull k2[DK][4];
    #pragma unroll
    for (int d = 0; d < DK; d++) {
        ulonglong2 t = *(const ulonglong2*)(kg + d*SQ + j0);
        k2[d][0] = t.x; k2[d][1] = t.y;
        ulonglong2 u = *(const ulonglong2*)(kg + d*SQ + j1);
        k2[d][2] = u.x; k2[d][3] = u.y;
    }

    const float* bbase = bias     + ((size_t)bh*SQ + row0)*(size_t)SQ;
    float*       abase = attn_out + ((size_t)bh*SQ + row0)*(size_t)SQ;

    ull bc[2][4];
    ldcs2(bbase + j0,      bc[0][0], bc[0][1]);
    ldcs2(bbase + j1,      bc[0][2], bc[0][3]);
    ldcs2(bbase + SQ + j0, bc[1][0], bc[1][1]);
    ldcs2(bbase + SQ + j1, bc[1][2], bc[1][3]);

    float inv_prev0 = 0.f, inv_prev1 = 0.f;
    __syncthreads();   // Vsm ready

    for (int pair = 0; pair < 32; pair++) {
        int p3 = pair % 3;
        const float* qp = qg + pair*2*DK;
        ull q2[2][DK];
        #pragma unroll
        for (int r = 0; r < 2; r++)
            #pragma unroll
            for (int d = 0; d < DK; d++) {
                float qv = qp[r*DK + d];
                q2[r][d] = pack2(qv, qv);
            }

        ull e2[2][4], ce2[2][DK], ls2[2] = {0ull, 0ull};
        #pragma unroll
        for (int r = 0; r < 2; r++)
            #pragma unroll
            for (int d = 0; d < DK; d++) ce2[r][d] = 0ull;

        #pragma unroll
        for (int hf = 0; hf < 2; hf++) {
            int j = hf ? j1 : j0;
            #pragma unroll
            for (int r = 0; r < 2; r++) {
                #pragma unroll
                for (int c = 0; c < 2; c++) {
                    ull s2 = mul2(lam2, bc[r][hf*2+c]);
                    #pragma unroll
                    for (int d = 0; d < DK; d++) s2 = fma2(q2[r][d], k2[d][hf*2+c], s2);
                    float slo, shi; unpack2(s2, slo, shi);
                    ull e = pack2(ex2a(slo), ex2a(shi));
                    e2[r][hf*2+c] = e;
                    ls2[r] = add2(ls2[r], e);
                }
            }
            ull vd[DK][2];
            #pragma unroll
            for (int d = 0; d < DK; d++) {
                ulonglong2 t = *(const ulonglong2*)(Vsm + d*SQ + j);
                vd[d][0] = t.x; vd[d][1] = t.y;
            }
            #pragma unroll
            for (int r = 0; r < 2; r++)
                #pragma unroll
                for (int c = 0; c < 2; c++)
                    #pragma unroll
                    for (int d = 0; d < DK; d++)
                        ce2[r][d] = fma2(e2[r][hf*2+c], vd[d][c], ce2[r][d]);
        }

        // prefetch next pair's bias (bc fully consumed above)
        {
            int np = (pair < 31) ? pair + 1 : pair;
            const float* bn = bbase + (size_t)(np*2)*SQ;
            ldcs2(bn + j0,      bc[0][0], bc[0][1]);
            ldcs2(bn + j1,      bc[0][2], bc[0][3]);
            ldcs2(bn + SQ + j0, bc[1][0], bc[1][1]);
            ldcs2(bn + SQ + j1, bc[1][2], bc[1][3]);
        }

        // row sums -> warp reduce -> redb (double-buffered)
        float ls0, ls1;
        { float a, bq_; unpack2(ls2[0], a, bq_); ls0 = a + bq_;
          unpack2(ls2[1], a, bq_); ls1 = a + bq_; }
        #pragma unroll
        for (int o = 16; o; o >>= 1) {
            ls0 += __shfl_xor_sync(0xffffffffu, ls0, o);
            ls1 += __shfl_xor_sync(0xffffffffu, ls1, o);
        }
        if (lane == 0) ((float2*)redb)[(pair&1)*8 + wid] = make_float2(ls0, ls1);

        // ctx partials: horizontal + lane-pair reduce + STS (triple buffer)
        #pragma unroll
        for (int r = 0; r < 2; r++)
            #pragma unroll
            for (int d = 0; d < DK; d++) {
                float a, bq_; unpack2(ce2[r][d], a, bq_);
                float s = a + bq_;
                s += __shfl_xor_sync(0xffffffffu, s, 1);
                if (!(lane & 1)) part[(p3*10 + r*5 + d)*128 + (tid >> 1)] = s;
            }

        __syncthreads();   // the ONLY barrier per pair

        float t0 = 0.f, t1 = 0.f;
        {
            const float2* rp = (const float2*)redb + (pair&1)*8;
            #pragma unroll
            for (int w2 = 0; w2 < 8; w2++) { float2 v = rp[w2]; t0 += v.x; t1 += v.y; }
        }
        float inv0 = rcpa(t0), inv1 = rcpa(t1);

        // drain previous pair's ctx partials (race-free: triple buffer)
        if (pair > 0 && tid < 160) {
            int val = tid >> 4, piece = tid & 15;
            int pprev = (p3 == 0) ? 2 : p3 - 1;
            const float4* pp = (const float4*)(part + (pprev*10 + val)*128 + piece*8);
            float4 x = pp[0], y = pp[1];
            float s = ((x.x+x.y)+(x.z+x.w)) + ((y.x+y.y)+(y.z+y.w));
            unsigned m = 0xFFFFu << (lane & 16);
            s += __shfl_xor_sync(m, s, 8); s += __shfl_xor_sync(m, s, 4);
            s += __shfl_xor_sync(m, s, 2); s += __shfl_xor_sync(m, s, 1);
            if (piece == 0) {
                int r = (val >= 5), d = val - r*5;
                float ip = r ? inv_prev1 : inv_prev0;
                g_ctx[((size_t)b*SQ + row0 + (pair-1)*2 + r)*DI + hh*DK + d] = s * ip;
            }
        }

        // normalized attn store
        {
            ull i20 = pack2(inv0, inv0), i21 = pack2(inv1, inv1);
            float* a0 = abase + (size_t)(pair*2)*SQ;
            stcs2(a0 + j0,      mul2(e2[0][0], i20), mul2(e2[0][1], i20));
            stcs2(a0 + j1,      mul2(e2[0][2], i20), mul2(e2[0][3], i20));
            stcs2(a0 + SQ + j0, mul2(e2[1][0], i21), mul2(e2[1][1], i21));
            stcs2(a0 + SQ + j1, mul2(e2[1][2], i21), mul2(e2[1][3], i21));
        }
        inv_prev0 = inv0; inv_prev1 = inv1;
    }

    // final drain: pair 31 partials (p3 = 31%3 = 1); visible via last barrier
    if (tid < 160) {
        int val = tid >> 4, piece = tid & 15;
        const float4* pp = (const float4*)(part + ((31%3)*10 + val)*128 + piece*8);
        float4 x = pp[0], y = pp[1];
        float s = ((x.x+x.y)+(x.z+x.w)) + ((y.x+y.y)+(y.z+y.w));
        unsigned m = 0xFFFFu << (lane & 16);
        s += __shfl_xor_sync(m, s, 8); s += __shfl_xor_sync(m, s, 4);
        s += __shfl_xor_sync(m, s, 2); s += __shfl_xor_sync(m, s, 1);
        if (piece == 0) {
            int r = (val >= 5), d = val - r*5;
            float ip = r ? inv_prev1 : inv_prev0;
            g_ctx[((size_t)b*SQ + row0 + 62 + r)*DI + hh*DK + d] = s * ip;
        }
    }
}

// ---------------------------------------------------------------------------
// Kernel 3: out = residual + ctx @ Wo + bo. Warp-per-row, 16 rows/block.
// ---------------------------------------------------------------------------
__global__ __launch_bounds__(256) void out_kernel(
    const float* __restrict__ Qin, const float* __restrict__ Wo,
    const float* __restrict__ bo, float* __restrict__ out)
{
    __shared__ float Ws[DI*DM];
    __shared__ float bs[DM];
    __shared__ float Cs[16][DI];
    int tid = threadIdx.x;
    int rowbase = blockIdx.x * 16;
    for (int idx = tid; idx < DI*DM; idx += 256) Ws[idx] = Wo[idx];
    if (tid < DM) bs[tid] = bo[tid];
    for (int idx = tid; idx < 16*DI; idx += 256) Cs[idx/DI][idx%DI] = g_ctx[rowbase*DI + idx];
    __syncthreads();

    int w = tid >> 5, lane = tid & 31;
    #pragma unroll
    for (int rr = 0; rr < 2; rr++) {
        int r = w + rr*8;
        int rg = rowbase + r;
        float acc1 = bs[lane]      + Qin[rg*DM + lane];
        float acc2 = bs[lane + 32] + Qin[rg*DM + lane + 32];
        #pragma unroll 10
        for (int o = 0; o < DI; o++) {
            float c = Cs[r][o];
            acc1 = fmaf(c, Ws[o*DM + lane],      acc1);
            acc2 = fmaf(c, Ws[o*DM + lane + 32], acc2);
        }
        out[rg*DM + lane]      = acc1;
        out[rg*DM + lane + 32] = acc2;
    }
}

// ---------------------------------------------------------------------------
extern "C" void kernel_launch(void* const* d_in, const int* in_sizes, int n_in,
                              void* d_out, int out_size)
{
    const float* Q    = (const float*)d_in[0];
    const float* K    = (const float*)d_in[1];
    const float* V    = (const float*)d_in[2];
    const float* bias = (const float*)d_in[3];
    const float* lam  = (const float*)d_in[4];
    const float* Wq   = (const float*)d_in[5];
    const float* bq   = (const float*)d_in[6];
    const float* Wk   = (const float*)d_in[7];
    const float* bk   = (const float*)d_in[8];
    const float* Wv   = (const float*)d_in[9];
    const float* bv   = (const float*)d_in[10];
    const float* Wo   = (const float*)d_in[11];
    const float* bo   = (const float*)d_in[12];

    float* out1 = (float*)d_out;                 // [B,S,64]
    float* attn = out1 + (size_t)BB*SQ*DM;       // [B,H,S,S]

    cudaFuncSetAttribute(attn_kernel, cudaFuncAttributeMaxDynamicSharedMemorySize,
                         ATTN_SMEM_BYTES);

    proj_kernel<<<dim3(BB*SQ/64, 3), 512>>>(Q, K, V, Wq, bq, Wk, bk, Wv, bv);
    attn_kernel<<<dim3(SQ/64, BHN), 256, ATTN_SMEM_BYTES>>>(bias, lam, attn);
    out_kernel<<<BB*SQ/16, 256>>>(Q, Wo, bo, out1);
}

// round 12
// speedup vs baseline: 1.7769x; 1.1013x over previous
#include <cuda_runtime.h>

#define SQ 2048
#define BB 2
#define NH 12
#define DK 5
#define DM 64
#define DI 60
#define BHN (BB*NH)   // 24

typedef unsigned long long ull;

__device__ __forceinline__ ull fma2(ull a, ull b, ull c){ ull d; asm("fma.rn.f32x2 %0,%1,%2,%3;":"=l"(d):"l"(a),"l"(b),"l"(c)); return d; }
__device__ __forceinline__ ull add2(ull a, ull b){ ull d; asm("add.rn.f32x2 %0,%1,%2;":"=l"(d):"l"(a),"l"(b)); return d; }
__device__ __forceinline__ ull mul2(ull a, ull b){ ull d; asm("mul.rn.f32x2 %0,%1,%2;":"=l"(d):"l"(a),"l"(b)); return d; }
__device__ __forceinline__ ull pack2(float lo, float hi){ ull d; asm("mov.b64 %0,{%1,%2};":"=l"(d):"f"(lo),"f"(hi)); return d; }
__device__ __forceinline__ void unpack2(ull v, float& lo, float& hi){ asm("mov.b64 {%0,%1},%2;":"=f"(lo),"=f"(hi):"l"(v)); }
__device__ __forceinline__ float ex2a(float x){ float y; asm("ex2.approx.f32 %0,%1;":"=f"(y):"f"(x)); return y; }
__device__ __forceinline__ float rcpa(float x){ float y; asm("rcp.approx.f32 %0,%1;":"=f"(y):"f"(x)); return y; }
__device__ __forceinline__ void stcs2(float* p, ull a, ull b){ asm("st.global.cs.v2.b64 [%0],{%1,%2};"::"l"(p),"l"(a),"l"(b):"memory"); }

__device__ __forceinline__ unsigned smem_u32(const void* p){
    unsigned a; asm("{ .reg .u64 t; cvta.to.shared.u64 t, %1; cvt.u32.u64 %0, t; }":"=r"(a):"l"(p)); return a;
}
__device__ __forceinline__ void mbar_init(unsigned m, unsigned cnt){
    asm volatile("mbarrier.init.shared.b64 [%0], %1;"::"r"(m),"r"(cnt):"memory");
}
__device__ __forceinline__ void mbar_expect_tx(unsigned m, unsigned bytes){
    asm volatile("mbarrier.arrive.expect_tx.shared.b64 _, [%0], %1;"::"r"(m),"r"(bytes):"memory");
}
__device__ __forceinline__ void bulk_g2s(unsigned dst, const void* src, unsigned bytes, unsigned m){
    asm volatile("cp.async.bulk.shared::cta.global.mbarrier::complete_tx::bytes [%0], [%1], %2, [%3];"
                 ::"r"(dst),"l"(src),"r"(bytes),"r"(m):"memory");
}
__device__ __forceinline__ void mbar_wait(unsigned m, unsigned parity){
    unsigned done;
    asm volatile("{\n\t.reg .pred p;\n\t"
                 "mbarrier.try_wait.parity.acquire.cta.shared::cta.b64 p, [%1], %2;\n\t"
                 "selp.b32 %0, 1, 0, p;\n\t}"
                 :"=r"(done):"r"(m),"r"(parity):"memory");
    if (!done) {
        asm volatile("{\n\t.reg .pred P1;\n\t"
                     "WL_%=:\n\t"
                     "mbarrier.try_wait.parity.acquire.cta.shared::cta.b64 P1, [%0], %1, 0x989680;\n\t"
                     "@P1 bra.uni WD_%=;\n\t"
                     "bra.uni WL_%=;\n\t"
                     "WD_%=:\n\t}"
                     ::"r"(m),"r"(parity):"memory");
    }
}

// Scratch (device globals; no allocations allowed)
__device__ float g_q[BHN*SQ*DK];    // [B,H,S,DK], pre-scaled by log2e/sqrt(DK)
__device__ float g_k[BHN*DK*SQ];    // [B,H,DK,S]
__device__ float g_v[BHN*DK*SQ];    // [B,H,DK,S]
__device__ float g_ctx[BB*SQ*DI];   // [B,S,60]

// ---------------------------------------------------------------------------
// Kernel 1: QKV projections, warp-per-row. 64 rows/block, 512 threads,
// grid (64, 3). (R8 version, known-good.)
// ---------------------------------------------------------------------------
__global__ __launch_bounds__(512) void proj_kernel(
    const float* __restrict__ Q, const float* __restrict__ K, const float* __restrict__ V,
    const float* __restrict__ Wq, const float* __restrict__ bq,
    const float* __restrict__ Wk, const float* __restrict__ bk,
    const float* __restrict__ Wv, const float* __restrict__ bv)
{
    __shared__ float Ws[DM*DI];
    __shared__ float bs[DI];
    __shared__ float Xs[64][DM];

    int mode = blockIdx.y;
    const float* X; const float* W; const float* bvec;
    if (mode == 0)      { X = Q; W = Wq; bvec = bq; }
    else if (mode == 1) { X = K; W = Wk; bvec = bk; }
    else                { X = V; W = Wv; bvec = bv; }

    int rowbase = blockIdx.x * 64;
    int tid = threadIdx.x;

    for (int idx = tid; idx < DM*DI; idx += 512) Ws[idx] = W[idx];
    for (int idx = tid; idx < 1024; idx += 512)
        ((float4*)Xs)[idx] = ((const float4*)(X + rowbase*DM))[idx];
    if (tid < DI) bs[tid] = bvec[tid];
    __syncthreads();

    int w = tid >> 5, lane = tid & 31;
    int o2  = lane + 32;
    int o2c = (o2 < DI) ? o2 : 0;
    const float SCQ = 0.44721359549995793f * 1.4426950408889634f;

    #pragma unroll
    for (int rr = 0; rr < 4; rr++) {
        int r = w + rr*16;
        float acc1 = bs[lane];
        float acc2 = bs[o2c];
        #pragma unroll 8
        for (int m = 0; m < DM; m++) {
            float x = Xs[r][m];
            acc1 = fmaf(x, Ws[m*DI + lane], acc1);
            acc2 = fmaf(x, Ws[m*DI + o2c],  acc2);
        }
        int rg = rowbase + r;
        int b = rg >> 11, s = rg & (SQ-1);
        {
            int h = lane / DK, d = lane - h*DK;
            if (mode == 0)      g_q[((b*NH+h)*SQ + s)*DK + d] = acc1 * SCQ;
            else if (mode == 1) g_k[((b*NH+h)*DK + d)*SQ + s] = acc1;
            else                g_v[((b*NH+h)*DK + d)*SQ + s] = acc1;
        }
        if (o2 < DI) {
            int h = o2 / DK, d = o2 - h*DK;
            if (mode == 0)      g_q[((b*NH+h)*SQ + s)*DK + d] = acc2 * SCQ;
            else if (mode == 1) g_k[((b*NH+h)*DK + d)*SQ + s] = acc2;
            else                g_v[((b*NH+h)*DK + d)*SQ + s] = acc2;
        }
    }
}

// ---------------------------------------------------------------------------
// Kernel 2: fused attention. grid (32,24), 256 threads, 2 blocks/SM.
// K in registers; V in smem. Bias streamed via 3-stage cp.async.bulk
// (16KB = 2 rows/stage) into smem with mbarrier expect_tx; consumers
// try_wait parity and read via LDS. Existing per-pair __syncthreads provides
// refill backpressure (slot p%3 refilled for pair p+3). One barrier/pair.
// ---------------------------------------------------------------------------
// dynamic smem layout (floats):
//   [0..7]        mbar[3] (+pad)
//   [8..10247]    Vsm [5][2048]
//   [10248..22535] bias stages [3][4096]
//   [22536..26375] part [3][10][128]
//   [26376..26407] redb [2][8] float2
#define SM_MBAR  0
#define SM_V     8
#define SM_BIAS  (SM_V + 5*SQ)
#define SM_PART  (SM_BIAS + 3*2*SQ)
#define SM_REDB  (SM_PART + 3*10*128)
#define ATTN_SMEM_FLOATS (SM_REDB + 32)
#define ATTN_SMEM_BYTES  (ATTN_SMEM_FLOATS*4)
#define STAGE_BYTES (2*SQ*4)

__global__ __launch_bounds__(256, 2) void attn_kernel(
    const float* __restrict__ bias,
    const float* __restrict__ lam_p,
    float* __restrict__ attn_out)
{
    extern __shared__ float sm[];
    float* Vsm  = sm + SM_V;
    float* bsm  = sm + SM_BIAS;
    float* part = sm + SM_PART;
    float* redb = sm + SM_REDB;
    unsigned mbar0 = smem_u32(sm + SM_MBAR);

    int bh = blockIdx.y, row0 = blockIdx.x*64;
    int tid = threadIdx.x, lane = tid & 31, wid = tid >> 5;
    float laml = lam_p[0] * 1.4426950408889634f;
    ull lam2 = pack2(laml, laml);

    const float* kg = g_k + (size_t)bh*DK*SQ;
    const float* vg = g_v + (size_t)bh*DK*SQ;
    const float* qg = g_q + ((size_t)bh*SQ + row0)*DK;
    int b = bh / NH, hh = bh % NH;

    for (int i = tid; i < DK*SQ/4; i += 256)
        ((float4*)Vsm)[i] = ((const float4*)vg)[i];

    int j0 = tid*4, j1 = 1024 + tid*4;

    // K held in registers for all 32 pairs: [d][half*2+colpair]
    ull k2[DK][4];
    #pragma unroll
    for (int d = 0; d < DK; d++) {
        ulonglong2 t = *(const ulonglong2*)(kg + d*SQ + j0);
        k2[d][0] = t.x; k2[d][1] = t.y;
        ulonglong2 u = *(const ulonglong2*)(kg + d*SQ + j1);
        k2[d][2] = u.x; k2[d][3] = u.y;
    }

    const float* bbase = bias     + ((size_t)bh*SQ + row0)*(size_t)SQ;
    float*       abase = attn_out + ((size_t)bh*SQ + row0)*(size_t)SQ;

    if (tid == 0) {
        mbar_init(mbar0,      1);
        mbar_init(mbar0 + 8,  1);
        mbar_init(mbar0 + 16, 1);
    }
    __syncthreads();   // mbarriers + Vsm visible

    if (tid == 0) {
        #pragma unroll
        for (int s = 0; s < 3; s++) {
            unsigned m = mbar0 + s*8;
            mbar_expect_tx(m, STAGE_BYTES);
            bulk_g2s(smem_u32(bsm + s*2*SQ), bbase + (size_t)(s*2)*SQ, STAGE_BYTES, m);
        }
    }

    float inv_prev0 = 0.f, inv_prev1 = 0.f;

    for (int pair = 0; pair < 32; pair++) {
        int p3 = pair % 3;
        // wait for this pair's bias stage
        mbar_wait(mbar0 + p3*8, (unsigned)((pair/3) & 1));

        const float* bst = bsm + p3*2*SQ;
        ull bc[2][4];
        {
            ulonglong2 t0 = *(const ulonglong2*)(bst + j0);
            bc[0][0]=t0.x; bc[0][1]=t0.y;
            ulonglong2 t1 = *(const ulonglong2*)(bst + j1);
            bc[0][2]=t1.x; bc[0][3]=t1.y;
            ulonglong2 t2 = *(const ulonglong2*)(bst + SQ + j0);
            bc[1][0]=t2.x; bc[1][1]=t2.y;
            ulonglong2 t3 = *(const ulonglong2*)(bst + SQ + j1);
            bc[1][2]=t3.x; bc[1][3]=t3.y;
        }

        const float* qp = qg + pair*2*DK;
        ull q2[2][DK];
        #pragma unroll
        for (int r = 0; r < 2; r++)
            #pragma unroll
            for (int d = 0; d < DK; d++) {
                float qv = qp[r*DK + d];
                q2[r][d] = pack2(qv, qv);
            }

        ull e2[2][4], ce2[2][DK], ls2[2] = {0ull, 0ull};
        #pragma unroll
        for (int r = 0; r < 2; r++)
            #pragma unroll
            for (int d = 0; d < DK; d++) ce2[r][d] = 0ull;

        #pragma unroll
        for (int hf = 0; hf < 2; hf++) {
            int j = hf ? j1 : j0;
            #pragma unroll
            for (int r = 0; r < 2; r++) {
                #pragma unroll
                for (int c = 0; c < 2; c++) {
                    ull s2 = mul2(lam2, bc[r][hf*2+c]);
                    #pragma unroll
                    for (int d = 0; d < DK; d++) s2 = fma2(q2[r][d], k2[d][hf*2+c], s2);
                    float slo, shi; unpack2(s2, slo, shi);
                    ull e = pack2(ex2a(slo), ex2a(shi));
                    e2[r][hf*2+c] = e;
                    ls2[r] = add2(ls2[r], e);
                }
            }
            ull vd[DK][2];
            #pragma unroll
            for (int d = 0; d < DK; d++) {
                ulonglong2 t = *(const ulonglong2*)(Vsm + d*SQ + j);
                vd[d][0] = t.x; vd[d][1] = t.y;
            }
            #pragma unroll
            for (int r = 0; r < 2; r++)
                #pragma unroll
                for (int c = 0; c < 2; c++)
                    #pragma unroll
                    for (int d = 0; d < DK; d++)
                        ce2[r][d] = fma2(e2[r][hf*2+c], vd[d][c], ce2[r][d]);
        }

        // row sums -> warp reduce -> redb (double-buffered)
        float ls0, ls1;
        { float a, bq_; unpack2(ls2[0], a, bq_); ls0 = a + bq_;
          unpack2(ls2[1], a, bq_); ls1 = a + bq_; }
        #pragma unroll
        for (int o = 16; o; o >>= 1) {
            ls0 += __shfl_xor_sync(0xffffffffu, ls0, o);
            ls1 += __shfl_xor_sync(0xffffffffu, ls1, o);
        }
        if (lane == 0) ((float2*)redb)[(pair&1)*8 + wid] = make_float2(ls0, ls1);

        // ctx partials: horizontal + lane-pair reduce + STS (triple buffer)
        #pragma unroll
        for (int r = 0; r < 2; r++)
            #pragma unroll
            for (int d = 0; d < DK; d++) {
                float a, bq_; unpack2(ce2[r][d], a, bq_);
                float s = a + bq_;
                s += __shfl_xor_sync(0xffffffffu, s, 1);
                if (!(lane & 1)) part[(p3*10 + r*5 + d)*128 + (tid >> 1)] = s;
            }

        __syncthreads();   // the ONLY barrier per pair (also refill backpressure)

        // refill this stage for pair+3 (slot consumed by everyone above)
        if (tid == 0 && pair + 3 < 32) {
            unsigned m = mbar0 + p3*8;
            mbar_expect_tx(m, STAGE_BYTES);
            bulk_g2s(smem_u32(bsm + p3*2*SQ), bbase + (size_t)((pair+3)*2)*SQ, STAGE_BYTES, m);
        }

        float t0 = 0.f, t1 = 0.f;
        {
            const float2* rp = (const float2*)redb + (pair&1)*8;
            #pragma unroll
            for (int w2 = 0; w2 < 8; w2++) { float2 v = rp[w2]; t0 += v.x; t1 += v.y; }
        }
        float inv0 = rcpa(t0), inv1 = rcpa(t1);

        // drain previous pair's ctx partials (race-free: triple buffer)
        if (pair > 0 && tid < 160) {
            int val = tid >> 4, piece = tid & 15;
            int pprev = (p3 == 0) ? 2 : p3 - 1;
            const float4* pp = (const float4*)(part + (pprev*10 + val)*128 + piece*8);
            float4 x = pp[0], y = pp[1];
            float s = ((x.x+x.y)+(x.z+x.w)) + ((y.x+y.y)+(y.z+y.w));
            unsigned m = 0xFFFFu << (lane & 16);
            s += __shfl_xor_sync(m, s, 8); s += __shfl_xor_sync(m, s, 4);
            s += __shfl_xor_sync(m, s, 2); s += __shfl_xor_sync(m, s, 1);
            if (piece == 0) {
                int r = (val >= 5), d = val - r*5;
                float ip = r ? inv_prev1 : inv_prev0;
                g_ctx[((size_t)b*SQ + row0 + (pair-1)*2 + r)*DI + hh*DK + d] = s * ip;
            }
        }

        // normalized attn store
        {
            ull i20 = pack2(inv0, inv0), i21 = pack2(inv1, inv1);
            float* a0 = abase + (size_t)(pair*2)*SQ;
            stcs2(a0 + j0,      mul2(e2[0][0], i20), mul2(e2[0][1], i20));
            stcs2(a0 + j1,      mul2(e2[0][2], i20), mul2(e2[0][3], i20));
            stcs2(a0 + SQ + j0, mul2(e2[1][0], i21), mul2(e2[1][1], i21));
            stcs2(a0 + SQ + j1, mul2(e2[1][2], i21), mul2(e2[1][3], i21));
        }
        inv_prev0 = inv0; inv_prev1 = inv1;
    }

    // final drain: pair 31 partials (p3 = 31%3 = 1); visible via last barrier
    if (tid < 160) {
        int val = tid >> 4, piece = tid & 15;
        const float4* pp = (const float4*)(part + ((31%3)*10 + val)*128 + piece*8);
        float4 x = pp[0], y = pp[1];
        float s = ((x.x+x.y)+(x.z+x.w)) + ((y.x+y.y)+(y.z+y.w));
        unsigned m = 0xFFFFu << (lane & 16);
        s += __shfl_xor_sync(m, s, 8); s += __shfl_xor_sync(m, s, 4);
        s += __shfl_xor_sync(m, s, 2); s += __shfl_xor_sync(m, s, 1);
        if (piece == 0) {
            int r = (val >= 5), d = val - r*5;
            float ip = r ? inv_prev1 : inv_prev0;
            g_ctx[((size_t)b*SQ + row0 + 62 + r)*DI + hh*DK + d] = s * ip;
        }
    }
}

// ---------------------------------------------------------------------------
// Kernel 3: out = residual + ctx @ Wo + bo. Warp-per-row, 16 rows/block.
// ---------------------------------------------------------------------------
__global__ __launch_bounds__(256) void out_kernel(
    const float* __restrict__ Qin, const float* __restrict__ Wo,
    const float* __restrict__ bo, float* __restrict__ out)
{
    __shared__ float Ws[DI*DM];
    __shared__ float bs[DM];
    __shared__ float Cs[16][DI];
    int tid = threadIdx.x;
    int rowbase = blockIdx.x * 16;
    for (int idx = tid; idx < DI*DM; idx += 256) Ws[idx] = Wo[idx];
    if (tid < DM) bs[tid] = bo[tid];
    for (int idx = tid; idx < 16*DI; idx += 256) Cs[idx/DI][idx%DI] = g_ctx[rowbase*DI + idx];
    __syncthreads();

    int w = tid >> 5, lane = tid & 31;
    #pragma unroll
    for (int rr = 0; rr < 2; rr++) {
        int r = w + rr*8;
        int rg = rowbase + r;
        float acc1 = bs[lane]      + Qin[rg*DM + lane];
        float acc2 = bs[lane + 32] + Qin[rg*DM + lane + 32];
        #pragma unroll 10
        for (int o = 0; o < DI; o++) {
            float c = Cs[r][o];
            acc1 = fmaf(c, Ws[o*DM + lane],      acc1);
            acc2 = fmaf(c, Ws[o*DM + lane + 32], acc2);
        }
        out[rg*DM + lane]      = acc1;
        out[rg*DM + lane + 32] = acc2;
    }
}

// ---------------------------------------------------------------------------
extern "C" void kernel_launch(void* const* d_in, const int* in_sizes, int n_in,
                              void* d_out, int out_size)
{
    const float* Q    = (const float*)d_in[0];
    const float* K    = (const float*)d_in[1];
    const float* V    = (const float*)d_in[2];
    const float* bias = (const float*)d_in[3];
    const float* lam  = (const float*)d_in[4];
    const float* Wq   = (const float*)d_in[5];
    const float* bq   = (const float*)d_in[6];
    const float* Wk   = (const float*)d_in[7];
    const float* bk   = (const float*)d_in[8];
    const float* Wv   = (const float*)d_in[9];
    const float* bv   = (const float*)d_in[10];
    const float* Wo   = (const float*)d_in[11];
    const float* bo   = (const float*)d_in[12];

    float* out1 = (float*)d_out;                 // [B,S,64]
    float* attn = out1 + (size_t)BB*SQ*DM;       // [B,H,S,S]

    cudaFuncSetAttribute(attn_kernel, cudaFuncAttributeMaxDynamicSharedMemorySize,
                         ATTN_SMEM_BYTES);

    proj_kernel<<<dim3(BB*SQ/64, 3), 512>>>(Q, K, V, Wq, bq, Wk, bk, Wv, bv);
    attn_kernel<<<dim3(SQ/64, BHN), 256, ATTN_SMEM_BYTES>>>(bias, lam, attn);
    out_kernel<<<BB*SQ/16, 256>>>(Q, Wo, bo, out1);
}

// round 13
// speedup vs baseline: 1.8068x; 1.0168x over previous
#include <cuda_runtime.h>

#define SQ 2048
#define BB 2
#define NH 12
#define DK 5
#define DM 64
#define DI 60
#define BHN (BB*NH)   // 24
#define NTICK 768     // 24 heads * 32 tiles
#define NBLK 296      // 148 SMs * 2 blocks

typedef unsigned long long ull;

__device__ __forceinline__ ull fma2(ull a, ull b, ull c){ ull d; asm("fma.rn.f32x2 %0,%1,%2,%3;":"=l"(d):"l"(a),"l"(b),"l"(c)); return d; }
__device__ __forceinline__ ull add2(ull a, ull b){ ull d; asm("add.rn.f32x2 %0,%1,%2;":"=l"(d):"l"(a),"l"(b)); return d; }
__device__ __forceinline__ ull mul2(ull a, ull b){ ull d; asm("mul.rn.f32x2 %0,%1,%2;":"=l"(d):"l"(a),"l"(b)); return d; }
__device__ __forceinline__ ull pack2(float lo, float hi){ ull d; asm("mov.b64 %0,{%1,%2};":"=l"(d):"f"(lo),"f"(hi)); return d; }
__device__ __forceinline__ void unpack2(ull v, float& lo, float& hi){ asm("mov.b64 {%0,%1},%2;":"=f"(lo),"=f"(hi):"l"(v)); }
__device__ __forceinline__ float ex2a(float x){ float y; asm("ex2.approx.f32 %0,%1;":"=f"(y):"f"(x)); return y; }
__device__ __forceinline__ float rcpa(float x){ float y; asm("rcp.approx.f32 %0,%1;":"=f"(y):"f"(x)); return y; }
__device__ __forceinline__ void stcs2(float* p, ull a, ull b){ asm("st.global.cs.v2.b64 [%0],{%1,%2};"::"l"(p),"l"(a),"l"(b):"memory"); }

__device__ __forceinline__ unsigned smem_u32(const void* p){
    unsigned a; asm("{ .reg .u64 t; cvta.to.shared.u64 t, %1; cvt.u32.u64 %0, t; }":"=r"(a):"l"(p)); return a;
}
__device__ __forceinline__ void mbar_init(unsigned m, unsigned cnt){
    asm volatile("mbarrier.init.shared.b64 [%0], %1;"::"r"(m),"r"(cnt):"memory");
}
__device__ __forceinline__ void mbar_expect_tx(unsigned m, unsigned bytes){
    asm volatile("mbarrier.arrive.expect_tx.shared.b64 _, [%0], %1;"::"r"(m),"r"(bytes):"memory");
}
__device__ __forceinline__ void bulk_g2s(unsigned dst, const void* src, unsigned bytes, unsigned m){
    asm volatile("cp.async.bulk.shared::cta.global.mbarrier::complete_tx::bytes [%0], [%1], %2, [%3];"
                 ::"r"(dst),"l"(src),"r"(bytes),"r"(m):"memory");
}
__device__ __forceinline__ void mbar_wait(unsigned m, unsigned parity){
    unsigned done;
    asm volatile("{\n\t.reg .pred p;\n\t"
                 "mbarrier.try_wait.parity.acquire.cta.shared::cta.b64 p, [%1], %2;\n\t"
                 "selp.b32 %0, 1, 0, p;\n\t}"
                 :"=r"(done):"r"(m),"r"(parity):"memory");
    if (!done) {
        asm volatile("{\n\t.reg .pred P1;\n\t"
                     "WL_%=:\n\t"
                     "mbarrier.try_wait.parity.acquire.cta.shared::cta.b64 P1, [%0], %1, 0x989680;\n\t"
                     "@P1 bra.uni WD_%=;\n\t"
                     "bra.uni WL_%=;\n\t"
                     "WD_%=:\n\t}"
                     ::"r"(m),"r"(parity):"memory");
    }
}

// Scratch (device globals; no allocations allowed)
__device__ float g_q[BHN*SQ*DK];
__device__ float g_k[BHN*DK*SQ];
__device__ float g_v[BHN*DK*SQ];
__device__ float g_ctx[BB*SQ*DI];
__device__ int   g_ticket;

__global__ void tick_init_kernel() { g_ticket = NBLK; }

// ---------------------------------------------------------------------------
// Kernel 1: QKV projections (R8 version, known-good).
// ---------------------------------------------------------------------------
__global__ __launch_bounds__(512) void proj_kernel(
    const float* __restrict__ Q, const float* __restrict__ K, const float* __restrict__ V,
    const float* __restrict__ Wq, const float* __restrict__ bq,
    const float* __restrict__ Wk, const float* __restrict__ bk,
    const float* __restrict__ Wv, const float* __restrict__ bv)
{
    __shared__ float Ws[DM*DI];
    __shared__ float bs[DI];
    __shared__ float Xs[64][DM];

    int mode = blockIdx.y;
    const float* X; const float* W; const float* bvec;
    if (mode == 0)      { X = Q; W = Wq; bvec = bq; }
    else if (mode == 1) { X = K; W = Wk; bvec = bk; }
    else                { X = V; W = Wv; bvec = bv; }

    int rowbase = blockIdx.x * 64;
    int tid = threadIdx.x;

    for (int idx = tid; idx < DM*DI; idx += 512) Ws[idx] = W[idx];
    for (int idx = tid; idx < 1024; idx += 512)
        ((float4*)Xs)[idx] = ((const float4*)(X + rowbase*DM))[idx];
    if (tid < DI) bs[tid] = bvec[tid];
    __syncthreads();

    int w = tid >> 5, lane = tid & 31;
    int o2  = lane + 32;
    int o2c = (o2 < DI) ? o2 : 0;
    const float SCQ = 0.44721359549995793f * 1.4426950408889634f;

    #pragma unroll
    for (int rr = 0; rr < 4; rr++) {
        int r = w + rr*16;
        float acc1 = bs[lane];
        float acc2 = bs[o2c];
        #pragma unroll 8
        for (int m = 0; m < DM; m++) {
            float x = Xs[r][m];
            acc1 = fmaf(x, Ws[m*DI + lane], acc1);
            acc2 = fmaf(x, Ws[m*DI + o2c],  acc2);
        }
        int rg = rowbase + r;
        int b = rg >> 11, s = rg & (SQ-1);
        {
            int h = lane / DK, d = lane - h*DK;
            if (mode == 0)      g_q[((b*NH+h)*SQ + s)*DK + d] = acc1 * SCQ;
            else if (mode == 1) g_k[((b*NH+h)*DK + d)*SQ + s] = acc1;
            else                g_v[((b*NH+h)*DK + d)*SQ + s] = acc1;
        }
        if (o2 < DI) {
            int h = o2 / DK, d = o2 - h*DK;
            if (mode == 0)      g_q[((b*NH+h)*SQ + s)*DK + d] = acc2 * SCQ;
            else if (mode == 1) g_k[((b*NH+h)*DK + d)*SQ + s] = acc2;
            else                g_v[((b*NH+h)*DK + d)*SQ + s] = acc2;
        }
    }
}

// ---------------------------------------------------------------------------
// Kernel 2: persistent-dynamic fused attention. 296 blocks x 256 threads,
// 2/SM. Tickets (head,64-row tile) via atomicAdd. Flat stage counter P:
// slot=P%3, parity=(P/3)&1; bias pipeline stays full across tile boundaries
// (refills at local pairs 29-31 target the prefetched next ticket).
// K in regs, V in smem, reloaded per tile. Compute identical to R12.
// ---------------------------------------------------------------------------
#define SM_MBAR  0
#define SM_TICK  6           // one int (in float slots; use index 6)
#define SM_V     8
#define SM_BIAS  (SM_V + 5*SQ)
#define SM_PART  (SM_BIAS + 3*2*SQ)
#define SM_REDB  (SM_PART + 3*10*128)
#define ATTN_SMEM_FLOATS (SM_REDB + 32)
#define ATTN_SMEM_BYTES  (ATTN_SMEM_FLOATS*4)
#define STAGE_BYTES (2*SQ*4)

__global__ __launch_bounds__(256, 2) void attn_kernel(
    const float* __restrict__ bias,
    const float* __restrict__ lam_p,
    float* __restrict__ attn_out)
{
    extern __shared__ float sm[];
    float* Vsm  = sm + SM_V;
    float* bsm  = sm + SM_BIAS;
    float* part = sm + SM_PART;
    float* redb = sm + SM_REDB;
    int*   stick = (int*)(sm + SM_TICK);
    unsigned mbar0 = smem_u32(sm + SM_MBAR);

    int tid = threadIdx.x, lane = tid & 31, wid = tid >> 5;
    float laml = lam_p[0] * 1.4426950408889634f;
    ull lam2 = pack2(laml, laml);
    int j0 = tid*4, j1 = 1024 + tid*4;

    if (tid == 0) {
        mbar_init(mbar0,      1);
        mbar_init(mbar0 + 8,  1);
        mbar_init(mbar0 + 16, 1);
    }
    __syncthreads();

    int cur = blockIdx.x;          // first ticket
    int P = 0;                     // flat stage counter

    // prefill stages 0,1,2 from ticket `cur` (tiles have 32 pairs > 3)
    if (tid == 0) {
        int bh0 = cur >> 5, tl0 = cur & 31;
        const float* bb0 = bias + ((size_t)bh0*SQ + tl0*64)*(size_t)SQ;
        #pragma unroll
        for (int s = 0; s < 3; s++) {
            unsigned m = mbar0 + s*8;
            mbar_expect_tx(m, STAGE_BYTES);
            bulk_g2s(smem_u32(bsm + s*2*SQ), bb0 + (size_t)(s*2)*SQ, STAGE_BYTES, m);
        }
    }

    while (cur < NTICK) {
        int bh = cur >> 5, row0 = (cur & 31) * 64;
        int b = bh / NH, hh = bh % NH;
        const float* kg = g_k + (size_t)bh*DK*SQ;
        const float* vg = g_v + (size_t)bh*DK*SQ;
        const float* qg = g_q + ((size_t)bh*SQ + row0)*DK;
        const float* bbase = bias     + ((size_t)bh*SQ + row0)*(size_t)SQ;
        float*       abase = attn_out + ((size_t)bh*SQ + row0)*(size_t)SQ;

        // reload V (prev tile's consumers all past last barrier) and K regs
        for (int i = tid; i < DK*SQ/4; i += 256)
            ((float4*)Vsm)[i] = ((const float4*)vg)[i];
        ull k2[DK][4];
        #pragma unroll
        for (int d = 0; d < DK; d++) {
            ulonglong2 t = *(const ulonglong2*)(kg + d*SQ + j0);
            k2[d][0] = t.x; k2[d][1] = t.y;
            ulonglong2 u = *(const ulonglong2*)(kg + d*SQ + j1);
            k2[d][2] = u.x; k2[d][3] = u.y;
        }
        int tn_loc = 0;
        if (tid == 0) { tn_loc = atomicAdd(&g_ticket, 1); *stick = tn_loc; }
        __syncthreads();   // Vsm + ticket visible
        int tick_next = *stick;
        const float* bbase_n = (tick_next < NTICK)
            ? bias + ((size_t)(tick_next >> 5)*SQ + (tick_next & 31)*64)*(size_t)SQ
            : (const float*)0;

        float inv_prev0 = 0.f, inv_prev1 = 0.f;

        for (int lp = 0; lp < 32; lp++, P++) {
            int sl = P % 3;
            mbar_wait(mbar0 + sl*8, (unsigned)((P/3) & 1));

            const float* bst = bsm + sl*2*SQ;
            ull bc[2][4];
            {
                ulonglong2 t0 = *(const ulonglong2*)(bst + j0);
                bc[0][0]=t0.x; bc[0][1]=t0.y;
                ulonglong2 t1 = *(const ulonglong2*)(bst + j1);
                bc[0][2]=t1.x; bc[0][3]=t1.y;
                ulonglong2 t2 = *(const ulonglong2*)(bst + SQ + j0);
                bc[1][0]=t2.x; bc[1][1]=t2.y;
                ulonglong2 t3 = *(const ulonglong2*)(bst + SQ + j1);
                bc[1][2]=t3.x; bc[1][3]=t3.y;
            }

            const float* qp = qg + lp*2*DK;
            ull q2[2][DK];
            #pragma unroll
            for (int r = 0; r < 2; r++)
                #pragma unroll
                for (int d = 0; d < DK; d++) {
                    float qv = qp[r*DK + d];
                    q2[r][d] = pack2(qv, qv);
                }

            ull e2[2][4], ce2[2][DK], ls2[2] = {0ull, 0ull};
            #pragma unroll
            for (int r = 0; r < 2; r++)
                #pragma unroll
                for (int d = 0; d < DK; d++) ce2[r][d] = 0ull;

            #pragma unroll
            for (int hf = 0; hf < 2; hf++) {
                int j = hf ? j1 : j0;
                #pragma unroll
                for (int r = 0; r < 2; r++) {
                    #pragma unroll
                    for (int c = 0; c < 2; c++) {
                        ull s2 = mul2(lam2, bc[r][hf*2+c]);
                        #pragma unroll
                        for (int d = 0; d < DK; d++) s2 = fma2(q2[r][d], k2[d][hf*2+c], s2);
                        float slo, shi; unpack2(s2, slo, shi);
                        ull e = pack2(ex2a(slo), ex2a(shi));
                        e2[r][hf*2+c] = e;
                        ls2[r] = add2(ls2[r], e);
                    }
                }
                ull vd[DK][2];
                #pragma unroll
                for (int d = 0; d < DK; d++) {
                    ulonglong2 t = *(const ulonglong2*)(Vsm + d*SQ + j);
                    vd[d][0] = t.x; vd[d][1] = t.y;
                }
                #pragma unroll
                for (int r = 0; r < 2; r++)
                    #pragma unroll
                    for (int c = 0; c < 2; c++)
                        #pragma unroll
                        for (int d = 0; d < DK; d++)
                            ce2[r][d] = fma2(e2[r][hf*2+c], vd[d][c], ce2[r][d]);
            }

            float ls0, ls1;
            { float a, bq_; unpack2(ls2[0], a, bq_); ls0 = a + bq_;
              unpack2(ls2[1], a, bq_); ls1 = a + bq_; }
            #pragma unroll
            for (int o = 16; o; o >>= 1) {
                ls0 += __shfl_xor_sync(0xffffffffu, ls0, o);
                ls1 += __shfl_xor_sync(0xffffffffu, ls1, o);
            }
            if (lane == 0) ((float2*)redb)[(lp&1)*8 + wid] = make_float2(ls0, ls1);

            #pragma unroll
            for (int r = 0; r < 2; r++)
                #pragma unroll
                for (int d = 0; d < DK; d++) {
                    float a, bq_; unpack2(ce2[r][d], a, bq_);
                    float s = a + bq_;
                    s += __shfl_xor_sync(0xffffffffu, s, 1);
                    if (!(lane & 1)) part[(sl*10 + r*5 + d)*128 + (tid >> 1)] = s;
                }

            __syncthreads();   // the ONLY barrier per pair

            // refill slot sl for flat stage P+3 (may be next ticket's rows)
            if (tid == 0) {
                int pl = lp + 3;
                const float* src = (const float*)0;
                if (pl < 32)            src = bbase   + (size_t)(pl*2)*SQ;
                else if (bbase_n)       src = bbase_n + (size_t)((pl-32)*2)*SQ;
                if (src) {
                    unsigned m = mbar0 + sl*8;
                    mbar_expect_tx(m, STAGE_BYTES);
                    bulk_g2s(smem_u32(bsm + sl*2*SQ), src, STAGE_BYTES, m);
                }
            }

            float t0 = 0.f, t1 = 0.f;
            {
                const float2* rp = (const float2*)redb + (lp&1)*8;
                #pragma unroll
                for (int w2 = 0; w2 < 8; w2++) { float2 v = rp[w2]; t0 += v.x; t1 += v.y; }
            }
            float inv0 = rcpa(t0), inv1 = rcpa(t1);

            if (lp > 0 && tid < 160) {
                int val = tid >> 4, piece = tid & 15;
                int pprev = (sl == 0) ? 2 : sl - 1;
                const float4* pp = (const float4*)(part + (pprev*10 + val)*128 + piece*8);
                float4 x = pp[0], y = pp[1];
                float s = ((x.x+x.y)+(x.z+x.w)) + ((y.x+y.y)+(y.z+y.w));
                unsigned m = 0xFFFFu << (lane & 16);
                s += __shfl_xor_sync(m, s, 8); s += __shfl_xor_sync(m, s, 4);
                s += __shfl_xor_sync(m, s, 2); s += __shfl_xor_sync(m, s, 1);
                if (piece == 0) {
                    int r = (val >= 5), d = val - r*5;
                    float ip = r ? inv_prev1 : inv_prev0;
                    g_ctx[((size_t)b*SQ + row0 + (lp-1)*2 + r)*DI + hh*DK + d] = s * ip;
                }
            }

            {
                ull i20 = pack2(inv0, inv0), i21 = pack2(inv1, inv1);
                float* a0 = abase + (size_t)(lp*2)*SQ;
                stcs2(a0 + j0,      mul2(e2[0][0], i20), mul2(e2[0][1], i20));
                stcs2(a0 + j1,      mul2(e2[0][2], i20), mul2(e2[0][3], i20));
                stcs2(a0 + SQ + j0, mul2(e2[1][0], i21), mul2(e2[1][1], i21));
                stcs2(a0 + SQ + j1, mul2(e2[1][2], i21), mul2(e2[1][3], i21));
            }
            inv_prev0 = inv0; inv_prev1 = inv1;
        }

        // final drain of this tile's pair 31 (slot (P-1)%3; after last barrier)
        if (tid < 160) {
            int sl31 = (P-1) % 3;
            int val = tid >> 4, piece = tid & 15;
            const float4* pp = (const float4*)(part + (sl31*10 + val)*128 + piece*8);
            float4 x = pp[0], y = pp[1];
            float s = ((x.x+x.y)+(x.z+x.w)) + ((y.x+y.y)+(y.z+y.w));
            unsigned m = 0xFFFFu << (lane & 16);
            s += __shfl_xor_sync(m, s, 8); s += __shfl_xor_sync(m, s, 4);
            s += __shfl_xor_sync(m, s, 2); s += __shfl_xor_sync(m, s, 1);
            if (piece == 0) {
                int r = (val >= 5), d = val - r*5;
                float ip = r ? inv_prev1 : inv_prev0;
                g_ctx[((size_t)b*SQ + row0 + 62 + r)*DI + hh*DK + d] = s * ip;
            }
        }

        cur = tick_next;
    }
}

// ---------------------------------------------------------------------------
// Kernel 3: out = residual + ctx @ Wo + bo. Warp-per-row, 16 rows/block.
// ---------------------------------------------------------------------------
__global__ __launch_bounds__(256) void out_kernel(
    const float* __restrict__ Qin, const float* __restrict__ Wo,
    const float* __restrict__ bo, float* __restrict__ out)
{
    __shared__ float Ws[DI*DM];
    __shared__ float bs[DM];
    __shared__ float Cs[16][DI];
    int tid = threadIdx.x;
    int rowbase = blockIdx.x * 16;
    for (int idx = tid; idx < DI*DM; idx += 256) Ws[idx] = Wo[idx];
    if (tid < DM) bs[tid] = bo[tid];
    for (int idx = tid; idx < 16*DI; idx += 256) Cs[idx/DI][idx%DI] = g_ctx[rowbase*DI + idx];
    __syncthreads();

    int w = tid >> 5, lane = tid & 31;
    #pragma unroll
    for (int rr = 0; rr < 2; rr++) {
        int r = w + rr*8;
        int rg = rowbase + r;
        float acc1 = bs[lane]      + Qin[rg*DM + lane];
        float acc2 = bs[lane + 32] + Qin[rg*DM + lane + 32];
        #pragma unroll 10
        for (int o = 0; o < DI; o++) {
            float c = Cs[r][o];
            acc1 = fmaf(c, Ws[o*DM + lane],      acc1);
            acc2 = fmaf(c, Ws[o*DM + lane + 32], acc2);
        }
        out[rg*DM + lane]      = acc1;
        out[rg*DM + lane + 32] = acc2;
    }
}

// ---------------------------------------------------------------------------
extern "C" void kernel_launch(void* const* d_in, const int* in_sizes, int n_in,
                              void* d_out, int out_size)
{
    const float* Q    = (const float*)d_in[0];
    const float* K    = (const float*)d_in[1];
    const float* V    = (const float*)d_in[2];
    const float* bias = (const float*)d_in[3];
    const float* lam  = (const float*)d_in[4];
    const float* Wq   = (const float*)d_in[5];
    const float* bq   = (const float*)d_in[6];
    const float* Wk   = (const float*)d_in[7];
    const float* bk   = (const float*)d_in[8];
    const float* Wv   = (const float*)d_in[9];
    const float* bv   = (const float*)d_in[10];
    const float* Wo   = (const float*)d_in[11];
    const float* bo   = (const float*)d_in[12];

    float* out1 = (float*)d_out;                 // [B,S,64]
    float* attn = out1 + (size_t)BB*SQ*DM;       // [B,H,S,S]

    cudaFuncSetAttribute(attn_kernel, cudaFuncAttributeMaxDynamicSharedMemorySize,
                         ATTN_SMEM_BYTES);

    proj_kernel<<<dim3(BB*SQ/64, 3), 512>>>(Q, K, V, Wq, bq, Wk, bk, Wv, bv);
    tick_init_kernel<<<1, 1>>>();
    attn_kernel<<<NBLK, 256, ATTN_SMEM_BYTES>>>(bias, lam, attn);
    out_kernel<<<BB*SQ/16, 256>>>(Q, Wo, bo, out1);
}